// round 11
// baseline (speedup 1.0000x reference)
#include <cuda_runtime.h>

// Problem constants (from reference)
#define B        4096
#define N_ELEM   2048
#define N_NODES  1024
#define E2       4096
#define G        2                     // batches per group
#define NGROUPS  (B / G)               // 2048 groups
#define NBLK     152                   // 1 CTA/SM, persistent
#define THREADS  1024
#define LANES    2
#define LTH      (THREADS / LANES)     // 512 threads per lane
#define NSTREAMS (NBLK * LANES)        // 304 independent group streams

// __device__ scratch (16B-aligned for cp.async.bulk sources).
__device__ __align__(16) float4 g_csr[E2];          // {eid_bits, vx, vy, 0}
__device__ __align__(16) int    g_off[N_NODES + 4];
__device__ float g_part[NBLK];
__device__ int   g_ctr = 0;

// Dynamic smem layout (bytes), 224KB total, 1 CTA/SM:
#define OFF_CSR    0                    // float4[E2]           64K (shared)
#define OFF_AX0    (64  * 1024)         // lane0 axial float2   16K
#define OFF_B0A    (80  * 1024)         // lane0 buf A          32K
#define OFF_B0B    (112 * 1024)         // lane0 buf B          32K
#define OFF_AX1    (144 * 1024)         // lane1 axial          16K
#define OFF_B1A    (160 * 1024)         // lane1 buf A          32K
#define OFF_B1B    (192 * 1024)         // lane1 buf B          32K
#define SMEM_BYTES (224 * 1024)

#define CSR_BYTES   (E2 * 16)            // 65536
#define HALF_BYTES  (G * N_ELEM * 4)     // 16384 (EA rows or e rows)
#define GRP_BYTES   (2 * HALF_BYTES)     // 32768 per group

__device__ __forceinline__ unsigned smem_u32(const void* p) {
    return (unsigned)__cvta_generic_to_shared(p);
}
__device__ __forceinline__ void mbar_init(unsigned mbar, unsigned count) {
    asm volatile("mbarrier.init.shared.b64 [%0], %1;" :: "r"(mbar), "r"(count) : "memory");
}
__device__ __forceinline__ void mbar_expect_tx(unsigned mbar, unsigned bytes) {
    asm volatile("mbarrier.arrive.expect_tx.shared.b64 _, [%0], %1;"
                 :: "r"(mbar), "r"(bytes) : "memory");
}
__device__ __forceinline__ void mbar_wait(unsigned mbar, unsigned parity) {
    asm volatile(
        "{\n\t.reg .pred P;\n\t"
        "W%=:\n\t"
        "mbarrier.try_wait.parity.acquire.cta.shared::cta.b64 P, [%0], %1, 0x989680;\n\t"
        "@!P bra W%=;\n\t}"
        :: "r"(mbar), "r"(parity) : "memory");
}
__device__ __forceinline__ void bulk_g2s(unsigned dst_smem, const void* src,
                                         unsigned bytes, unsigned mbar) {
    asm volatile(
        "cp.async.bulk.shared::cta.global.mbarrier::complete_tx::bytes [%0], [%1], %2, [%3];"
        :: "r"(dst_smem), "l"(src), "r"(bytes), "r"(mbar) : "memory");
}
__device__ __forceinline__ void lane_bar(int lane) {
    asm volatile("bar.sync %0, %1;" :: "r"(lane + 1), "r"(LTH) : "memory");
}

// ---------------------------------------------------------------------------
// Setup: deterministic CSR (edges grouped by node, sorted by original edge
// index within each node). One block, 1024 threads.
// ---------------------------------------------------------------------------
__global__ __launch_bounds__(N_NODES)
void nel_setup_kernel(const int* __restrict__ node_ids,
                      const int* __restrict__ elem_ids,
                      const float* __restrict__ vecs) {
    __shared__ int s_beg[N_NODES];
    __shared__ int s_cur[N_NODES];
    __shared__ int s_idx[E2];
    __shared__ int s_wsum[32];
    const int tid  = threadIdx.x;
    const int lane = tid & 31;
    const int wrp  = tid >> 5;

    // 1. histogram
    s_beg[tid] = 0;
    __syncthreads();
    #pragma unroll
    for (int i = tid; i < E2; i += N_NODES)
        atomicAdd(&s_beg[node_ids[i]], 1);
    __syncthreads();

    // 2. exclusive scan via warp shuffles
    const int cnt = s_beg[tid];
    int v = cnt;
    #pragma unroll
    for (int o = 1; o < 32; o <<= 1) {
        int t = __shfl_up_sync(0xffffffffu, v, o);
        if (lane >= o) v += t;
    }
    if (lane == 31) s_wsum[wrp] = v;
    __syncthreads();
    if (wrp == 0) {
        int w = s_wsum[lane];
        #pragma unroll
        for (int o = 1; o < 32; o <<= 1) {
            int t = __shfl_up_sync(0xffffffffu, w, o);
            if (lane >= o) w += t;
        }
        s_wsum[lane] = w - s_wsum[lane];
    }
    __syncthreads();
    const int excl = v - cnt + s_wsum[wrp];
    s_beg[tid] = excl;
    s_cur[tid] = excl;
    __syncthreads();

    // 3. scatter edge indices into bins
    #pragma unroll
    for (int i = tid; i < E2; i += N_NODES) {
        int pos = atomicAdd(&s_cur[node_ids[i]], 1);
        s_idx[pos] = i;
    }
    __syncthreads();

    // 4. per-bin insertion sort -> deterministic edge order
    {
        const int beg = s_beg[tid], end = s_cur[tid];
        for (int a = beg + 1; a < end; a++) {
            int key = s_idx[a];
            int p = a - 1;
            while (p >= beg && s_idx[p] > key) { s_idx[p + 1] = s_idx[p]; p--; }
            s_idx[p + 1] = key;
        }
    }
    __syncthreads();

    // 5. write fused CSR records + offsets
    g_off[tid] = s_beg[tid];
    if (tid == 0) {
        g_off[N_NODES] = E2; g_off[N_NODES + 1] = E2;
        g_off[N_NODES + 2] = E2; g_off[N_NODES + 3] = E2;
    }
    #pragma unroll
    for (int i = tid; i < E2; i += N_NODES) {
        int idx = s_idx[i];
        float4 rec;
        rec.x = __int_as_float(elem_ids[idx]);
        rec.y = vecs[2 * idx];
        rec.z = vecs[2 * idx + 1];
        rec.w = 0.f;
        g_csr[i] = rec;
    }
}

// ---------------------------------------------------------------------------
// Main: 152 persistent blocks (1/SM), 1024 threads split into 2 INDEPENDENT
// 512-thread lanes. Each lane runs its own G=2 group stream (own TMA double
// buffer, own mbarriers, named barriers) -> one lane's compute hides the
// other's waits/tails. CSR shared in smem.
// ---------------------------------------------------------------------------
__global__ __launch_bounds__(THREADS, 1)
void nel_main_kernel(const float* __restrict__ EA,
                     const float* __restrict__ e,
                     const float* __restrict__ q,
                     const float* __restrict__ r,
                     float* __restrict__ out) {
    extern __shared__ unsigned char dyn[];
    float4* s_csr = (float4*)(dyn + OFF_CSR);
    __shared__ __align__(8) unsigned long long s_mbar[5]; // csr, L0A, L0B, L1A, L1B
    __shared__ float s_warp[THREADS / 32];
    __shared__ int   s_islast;

    const int tid  = threadIdx.x;
    const int lane = tid / LTH;          // 0 or 1
    const int ltid = tid % LTH;

    float2* s_axial = (float2*)(dyn + (lane ? OFF_AX1 : OFF_AX0));
    float*  s_bufA  = (float*) (dyn + (lane ? OFF_B1A : OFF_B0A));
    float*  s_bufB  = (float*) (dyn + (lane ? OFF_B1B : OFF_B0B));
    const unsigned mb_csr = smem_u32(&s_mbar[0]);
    const unsigned mbA    = smem_u32(&s_mbar[1 + lane * 2]);
    const unsigned mbB    = smem_u32(&s_mbar[2 + lane * 2]);

    if (tid == 0) {
        mbar_init(mb_csr, 1);
        mbar_init(smem_u32(&s_mbar[1]), 1); mbar_init(smem_u32(&s_mbar[2]), 1);
        mbar_init(smem_u32(&s_mbar[3]), 1); mbar_init(smem_u32(&s_mbar[4]), 1);
    }
    __syncthreads();

    // this lane's group stream: g0, g0+NSTREAMS, ...
    const int g0  = blockIdx.x * LANES + lane;
    const int cnt = (g0 < NGROUPS) ? (NGROUPS - g0 + NSTREAMS - 1) / NSTREAMS : 0;

    // node spans (offsets from L2, batch-invariant); 2 nodes per thread
    const int n0 = ltid, n1 = ltid + LTH;
    const int beg0 = __ldg(&g_off[n0]), end0 = __ldg(&g_off[n0 + 1]);
    const int beg1 = __ldg(&g_off[n1]), end1 = __ldg(&g_off[n1 + 1]);

    // --- prologue: CSR (lane0's thread 0) + each lane's first two groups ---
    if (tid == 0) {
        mbar_expect_tx(mb_csr, CSR_BYTES);
        bulk_g2s(smem_u32(s_csr), g_csr, CSR_BYTES, mb_csr);
    }
    if (ltid == 0) {
        if (cnt > 0) {
            int grp = g0;
            mbar_expect_tx(mbA, GRP_BYTES);
            bulk_g2s(smem_u32(s_bufA),
                     EA + (size_t)grp * G * N_ELEM, HALF_BYTES, mbA);
            bulk_g2s(smem_u32(s_bufA + G * N_ELEM),
                     e  + (size_t)grp * G * N_ELEM, HALF_BYTES, mbA);
        }
        if (cnt > 1) {
            int grp = g0 + NSTREAMS;
            mbar_expect_tx(mbB, GRP_BYTES);
            bulk_g2s(smem_u32(s_bufB),
                     EA + (size_t)grp * G * N_ELEM, HALF_BYTES, mbB);
            bulk_g2s(smem_u32(s_bufB + G * N_ELEM),
                     e  + (size_t)grp * G * N_ELEM, HALF_BYTES, mbB);
        }
    }

    // wait for CSR once (arrives quickly; per-lane pipelines proceed after)
    mbar_wait(mb_csr, 0);

    float acc = 0.f;
    unsigned phA = 0, phB = 0;

    for (int k = 0; k < cnt; k++) {
        const int grp  = g0 + k * NSTREAMS;
        const int bsel = k & 1;
        float* buf = bsel ? s_bufB : s_bufA;
        const unsigned mb = bsel ? mbB : mbA;

        // --- early-issue q/r loads (independent; hide under build/gather) ---
        const float2* q2 = (const float2*)(q + (size_t)grp * G * N_NODES * 2);
        const float2* r2 = (const float2*)(r + (size_t)grp * G * N_NODES * 2);
        const float2 q00 = __ldg(&q2[n0]);            const float2 r00 = __ldg(&r2[n0]);
        const float2 q01 = __ldg(&q2[N_NODES + n0]);  const float2 r01 = __ldg(&r2[N_NODES + n0]);
        const float2 q10 = __ldg(&q2[n1]);            const float2 r10 = __ldg(&r2[n1]);
        const float2 q11 = __ldg(&q2[N_NODES + n1]);  const float2 r11 = __ldg(&r2[N_NODES + n1]);

        if (bsel) { mbar_wait(mb, phB); phB ^= 1; }
        else      { mbar_wait(mb, phA); phA ^= 1; }

        // --- build axial[i] = {EA_b0*e_b0, EA_b1*e_b1} (lane-local) ---
        #pragma unroll
        for (int i = ltid; i < N_ELEM; i += LTH) {
            float a0 = buf[i]          * buf[2 * N_ELEM + i];
            float a1 = buf[N_ELEM + i] * buf[3 * N_ELEM + i];
            s_axial[i] = make_float2(a0, a1);
        }
        lane_bar(lane);           // axial ready within this lane; buf free

        // --- refill this buffer with group k+2 (overlaps gather) ---
        if (ltid == 0 && k + 2 < cnt) {
            int ng = g0 + (k + 2) * NSTREAMS;
            mbar_expect_tx(mb, GRP_BYTES);
            bulk_g2s(smem_u32(buf),
                     EA + (size_t)ng * G * N_ELEM, HALF_BYTES, mb);
            bulk_g2s(smem_u32(buf + G * N_ELEM),
                     e  + (size_t)ng * G * N_ELEM, HALF_BYTES, mb);
        }

        // --- gather + loss, 2 nodes, 2 batches ---
        float ax0 = 0.f, ay0 = 0.f, bx0 = 0.f, by0 = 0.f;
        for (int p = beg0; p < end0; p++) {
            float4 rec = s_csr[p];
            float2 a   = s_axial[__float_as_int(rec.x)];
            ax0 += a.x * rec.y;  ay0 += a.x * rec.z;
            bx0 += a.y * rec.y;  by0 += a.y * rec.z;
        }
        float ax1 = 0.f, ay1 = 0.f, bx1 = 0.f, by1 = 0.f;
        for (int p = beg1; p < end1; p++) {
            float4 rec = s_csr[p];
            float2 a   = s_axial[__float_as_int(rec.x)];
            ax1 += a.x * rec.y;  ay1 += a.x * rec.z;
            bx1 += a.y * rec.y;  by1 += a.y * rec.z;
        }
        {
            float dx, dy;
            dx = ax0 - q00.x - r00.x;  dy = ay0 - q00.y - r00.y;  acc += dx*dx + dy*dy;
            dx = bx0 - q01.x - r01.x;  dy = by0 - q01.y - r01.y;  acc += dx*dx + dy*dy;
            dx = ax1 - q10.x - r10.x;  dy = ay1 - q10.y - r10.y;  acc += dx*dx + dy*dy;
            dx = bx1 - q11.x - r11.x;  dy = by1 - q11.y - r11.y;  acc += dx*dx + dy*dy;
        }
        lane_bar(lane);           // axial consumed before next build
    }

    // --- block-wide reduce (all 1024 threads reach here) ---
    __syncthreads();
    #pragma unroll
    for (int o = 16; o > 0; o >>= 1)
        acc += __shfl_down_sync(0xffffffffu, acc, o);
    if ((tid & 31) == 0) s_warp[tid >> 5] = acc;
    __syncthreads();
    if (tid == 0) {
        float total = 0.f;
        #pragma unroll
        for (int w = 0; w < THREADS / 32; w++) total += s_warp[w];
        g_part[blockIdx.x] = total;
    }

    // --- last-block finalize (fixed-order double sum -> deterministic) ---
    __threadfence();
    if (tid == 0) {
        int old = atomicAdd(&g_ctr, 1);
        s_islast = (old == (int)gridDim.x - 1) ? 1 : 0;
    }
    __syncthreads();
    if (s_islast) {
        __threadfence();
        double* s_d = (double*)(dyn + OFF_CSR);   // overlay consumed CSR
        double d = 0.0;
        #pragma unroll
        for (int i = tid; i < NBLK; i += THREADS) d += (double)g_part[i];
        s_d[tid] = d;
        __syncthreads();
        #pragma unroll
        for (int s = THREADS / 2; s > 0; s >>= 1) {
            if (tid < s) s_d[tid] += s_d[tid + s];
            __syncthreads();
        }
        if (tid == 0) {
            out[0] = (float)(s_d[0] / ((double)B * (double)N_NODES * 2.0));
            g_ctr = 0;   // reset for next graph replay
        }
    }
}

extern "C" void kernel_launch(void* const* d_in, const int* in_sizes, int n_in,
                              void* d_out, int out_size) {
    const float* EA       = (const float*)d_in[0];
    const float* e        = (const float*)d_in[1];
    const float* q        = (const float*)d_in[2];
    const float* r        = (const float*)d_in[3];
    const float* vecs     = (const float*)d_in[4];
    const int*   node_ids = (const int*)d_in[5];
    const int*   elem_ids = (const int*)d_in[6];
    float* out = (float*)d_out;

    static int configured = 0;
    if (!configured) {
        cudaFuncSetAttribute(nel_main_kernel,
                             cudaFuncAttributeMaxDynamicSharedMemorySize,
                             SMEM_BYTES);
        configured = 1;
    }

    nel_setup_kernel<<<1, N_NODES>>>(node_ids, elem_ids, vecs);
    nel_main_kernel<<<NBLK, THREADS, SMEM_BYTES>>>(EA, e, q, r, out);
}

// round 12
// speedup vs baseline: 1.1346x; 1.1346x over previous
#include <cuda_runtime.h>

// Problem constants (from reference)
#define B        4096
#define N_ELEM   2048
#define N_NODES  1024
#define E2       4096
#define G        4                     // batches per group
#define NGROUPS  (B / G)               // 1024 groups
#define NBLK     152                   // 1 CTA/SM, persistent
#define THREADS  512                   // 2 nodes per thread

// __device__ scratch (16B-aligned for cp.async.bulk sources).
__device__ __align__(16) float4 g_csr[E2 + 4];      // + dummy zero records
__device__ __align__(16) int    g_off[N_NODES + 4];
__device__ float g_part[NBLK];
__device__ int   g_ctr = 0;

// Dynamic smem layout (bytes):
#define OFF_CSR    0                    // float4[E2+4] = 65600 (reserve 65792)
#define OFF_AXIAL  65792                // float4[2048] = 32768
#define OFF_BUF0   98560                // 64K: [EA g0..g3 | e g0..g3]
#define OFF_BUF1   164096               // 64K
#define SMEM_BYTES 229632               // <= 232448 limit

#define CSR_BYTES   ((E2 + 4) * 16)      // 65600
#define GRP_BYTES   (2 * G * N_ELEM * 4) // 65536

__device__ __forceinline__ unsigned smem_u32(const void* p) {
    return (unsigned)__cvta_generic_to_shared(p);
}
__device__ __forceinline__ void mbar_init(unsigned mbar, unsigned count) {
    asm volatile("mbarrier.init.shared.b64 [%0], %1;" :: "r"(mbar), "r"(count) : "memory");
}
__device__ __forceinline__ void mbar_expect_tx(unsigned mbar, unsigned bytes) {
    asm volatile("mbarrier.arrive.expect_tx.shared.b64 _, [%0], %1;"
                 :: "r"(mbar), "r"(bytes) : "memory");
}
__device__ __forceinline__ void mbar_wait(unsigned mbar, unsigned parity) {
    asm volatile(
        "{\n\t.reg .pred P;\n\t"
        "W%=:\n\t"
        "mbarrier.try_wait.parity.acquire.cta.shared::cta.b64 P, [%0], %1, 0x989680;\n\t"
        "@!P bra W%=;\n\t}"
        :: "r"(mbar), "r"(parity) : "memory");
}
__device__ __forceinline__ void bulk_g2s(unsigned dst_smem, const void* src,
                                         unsigned bytes, unsigned mbar) {
    asm volatile(
        "cp.async.bulk.shared::cta.global.mbarrier::complete_tx::bytes [%0], [%1], %2, [%3];"
        :: "r"(dst_smem), "l"(src), "r"(bytes), "r"(mbar) : "memory");
}

// ---------------------------------------------------------------------------
// Setup: deterministic CSR (edges grouped by node, sorted by original edge
// index within each node) + trailing dummy zero records. One block.
// ---------------------------------------------------------------------------
__global__ __launch_bounds__(N_NODES)
void nel_setup_kernel(const int* __restrict__ node_ids,
                      const int* __restrict__ elem_ids,
                      const float* __restrict__ vecs) {
    __shared__ int s_beg[N_NODES];
    __shared__ int s_cur[N_NODES];
    __shared__ int s_idx[E2];
    __shared__ int s_wsum[32];
    const int tid  = threadIdx.x;
    const int lane = tid & 31;
    const int wrp  = tid >> 5;

    // 1. histogram
    s_beg[tid] = 0;
    __syncthreads();
    #pragma unroll
    for (int i = tid; i < E2; i += N_NODES)
        atomicAdd(&s_beg[node_ids[i]], 1);
    __syncthreads();

    // 2. exclusive scan via warp shuffles
    const int cnt = s_beg[tid];
    int v = cnt;
    #pragma unroll
    for (int o = 1; o < 32; o <<= 1) {
        int t = __shfl_up_sync(0xffffffffu, v, o);
        if (lane >= o) v += t;
    }
    if (lane == 31) s_wsum[wrp] = v;
    __syncthreads();
    if (wrp == 0) {
        int w = s_wsum[lane];
        #pragma unroll
        for (int o = 1; o < 32; o <<= 1) {
            int t = __shfl_up_sync(0xffffffffu, w, o);
            if (lane >= o) w += t;
        }
        s_wsum[lane] = w - s_wsum[lane];
    }
    __syncthreads();
    const int excl = v - cnt + s_wsum[wrp];
    s_beg[tid] = excl;
    s_cur[tid] = excl;
    __syncthreads();

    // 3. scatter edge indices into bins
    #pragma unroll
    for (int i = tid; i < E2; i += N_NODES) {
        int pos = atomicAdd(&s_cur[node_ids[i]], 1);
        s_idx[pos] = i;
    }
    __syncthreads();

    // 4. per-bin insertion sort -> deterministic edge order
    {
        const int beg = s_beg[tid], end = s_cur[tid];
        for (int a = beg + 1; a < end; a++) {
            int key = s_idx[a];
            int p = a - 1;
            while (p >= beg && s_idx[p] > key) { s_idx[p + 1] = s_idx[p]; p--; }
            s_idx[p + 1] = key;
        }
    }
    __syncthreads();

    // 5. write fused CSR records + offsets + dummy zero records
    g_off[tid] = s_beg[tid];
    if (tid == 0) {
        g_off[N_NODES] = E2; g_off[N_NODES + 1] = E2;
        g_off[N_NODES + 2] = E2; g_off[N_NODES + 3] = E2;
    }
    if (tid < 4) {
        // dummy: eid=0 (valid axial slot), weights 0 -> contributes nothing
        g_csr[E2 + tid] = make_float4(__int_as_float(0), 0.f, 0.f, 0.f);
    }
    #pragma unroll
    for (int i = tid; i < E2; i += N_NODES) {
        int idx = s_idx[i];
        float4 rec;
        rec.x = __int_as_float(elem_ids[idx]);
        rec.y = vecs[2 * idx];
        rec.z = vecs[2 * idx + 1];
        rec.w = 0.f;
        g_csr[i] = rec;
    }
}

// ---------------------------------------------------------------------------
// Main: 152 persistent blocks (1/SM), 512 threads, G=4 batches per group.
// Gather uses a warp-uniform bound + unroll-4 predicated body (dummy record
// for out-of-range slots) -> 4 independent LDS.128 chains in flight.
// ---------------------------------------------------------------------------
__global__ __launch_bounds__(THREADS, 1)
void nel_main_kernel(const float* __restrict__ EA,
                     const float* __restrict__ e,
                     const float* __restrict__ q,
                     const float* __restrict__ r,
                     float* __restrict__ out) {
    extern __shared__ unsigned char dyn[];
    float4* s_csr   = (float4*)(dyn + OFF_CSR);
    float4* s_axial = (float4*)(dyn + OFF_AXIAL);
    float*  s_buf0  = (float*) (dyn + OFF_BUF0);
    float*  s_buf1  = (float*) (dyn + OFF_BUF1);
    __shared__ __align__(8) unsigned long long s_mbar[2];
    __shared__ float s_warp[THREADS / 32];
    __shared__ int   s_islast;

    const int tid = threadIdx.x;
    const int g0  = blockIdx.x;
    const int cnt = (NGROUPS - g0 + NBLK - 1) / NBLK;
    const unsigned mb0 = smem_u32(&s_mbar[0]);
    const unsigned mb1 = smem_u32(&s_mbar[1]);

    if (tid == 0) { mbar_init(mb0, 1); mbar_init(mb1, 1); }
    __syncthreads();

    // node spans for this thread's 2 nodes (batch-invariant, from L2)
    const int n0 = tid, n1 = tid + THREADS;
    const int beg0 = __ldg(&g_off[n0]);
    const int len0 = __ldg(&g_off[n0 + 1]) - beg0;
    const int beg1 = __ldg(&g_off[n1]);
    const int len1 = __ldg(&g_off[n1 + 1]) - beg1;
    // warp-uniform iteration bounds (hoisted out of the group loop)
    int m0 = len0, m1 = len1;
    #pragma unroll
    for (int o = 16; o > 0; o >>= 1) {
        m0 = max(m0, __shfl_xor_sync(0xffffffffu, m0, o));
        m1 = max(m1, __shfl_xor_sync(0xffffffffu, m1, o));
    }

    // --- prologue: CSR + group 0 on mb0, group 1 on mb1 ---
    if (tid == 0) {
        {
            int grp = g0;
            mbar_expect_tx(mb0, CSR_BYTES + GRP_BYTES);
            bulk_g2s(smem_u32(s_csr), g_csr, CSR_BYTES, mb0);
            bulk_g2s(smem_u32(s_buf0),
                     EA + (size_t)grp * G * N_ELEM, G * N_ELEM * 4, mb0);
            bulk_g2s(smem_u32(s_buf0 + G * N_ELEM),
                     e  + (size_t)grp * G * N_ELEM, G * N_ELEM * 4, mb0);
        }
        if (cnt > 1) {
            int grp = g0 + NBLK;
            mbar_expect_tx(mb1, GRP_BYTES);
            bulk_g2s(smem_u32(s_buf1),
                     EA + (size_t)grp * G * N_ELEM, G * N_ELEM * 4, mb1);
            bulk_g2s(smem_u32(s_buf1 + G * N_ELEM),
                     e  + (size_t)grp * G * N_ELEM, G * N_ELEM * 4, mb1);
        }
    }

    float acc = 0.f;
    unsigned ph0 = 0, ph1 = 0;

    for (int k = 0; k < cnt; k++) {
        const int grp  = g0 + k * NBLK;
        const int bsel = k & 1;
        float* buf = bsel ? s_buf1 : s_buf0;
        const unsigned mb = bsel ? mb1 : mb0;

        // --- early-issue q/r loads (hide under build/gather) ---
        const float2* q2 = (const float2*)(q + (size_t)grp * G * N_NODES * 2);
        const float2* r2 = (const float2*)(r + (size_t)grp * G * N_NODES * 2);
        float2 qq0[G], rr0[G], qq1[G], rr1[G];
        #pragma unroll
        for (int g = 0; g < G; g++) {
            qq0[g] = __ldg(&q2[g * N_NODES + n0]);
            rr0[g] = __ldg(&r2[g * N_NODES + n0]);
            qq1[g] = __ldg(&q2[g * N_NODES + n1]);
            rr1[g] = __ldg(&r2[g * N_NODES + n1]);
        }

        if (bsel) { mbar_wait(mb, ph1); ph1 ^= 1; }
        else      { mbar_wait(mb, ph0); ph0 ^= 1; }

        // --- build axial4[i] = {EA_g*e_g} for g=0..3 ---
        #pragma unroll
        for (int i = tid; i < N_ELEM; i += THREADS) {
            float4 a;
            a.x = buf[0 * N_ELEM + i] * buf[(G + 0) * N_ELEM + i];
            a.y = buf[1 * N_ELEM + i] * buf[(G + 1) * N_ELEM + i];
            a.z = buf[2 * N_ELEM + i] * buf[(G + 2) * N_ELEM + i];
            a.w = buf[3 * N_ELEM + i] * buf[(G + 3) * N_ELEM + i];
            s_axial[i] = a;
        }
        __syncthreads();   // axial ready; buf free for refill

        // --- refill this buffer with group k+2 (overlaps gather) ---
        if (tid == 0 && k + 2 < cnt) {
            int ng = g0 + (k + 2) * NBLK;
            mbar_expect_tx(mb, GRP_BYTES);
            bulk_g2s(smem_u32(buf),
                     EA + (size_t)ng * G * N_ELEM, G * N_ELEM * 4, mb);
            bulk_g2s(smem_u32(buf + G * N_ELEM),
                     e  + (size_t)ng * G * N_ELEM, G * N_ELEM * 4, mb);
        }

        // --- gather node 0: warp-uniform bound, unroll-4 predicated ---
        float4 ax0 = make_float4(0.f, 0.f, 0.f, 0.f);
        float4 ay0 = make_float4(0.f, 0.f, 0.f, 0.f);
        for (int c = 0; c < m0; c += 4) {
            #pragma unroll
            for (int u = 0; u < 4; u++) {
                int off = c + u;
                int idx = (off < len0) ? (beg0 + off) : E2;   // dummy if past end
                float4 rec = s_csr[idx];
                float4 a   = s_axial[__float_as_int(rec.x)];
                ax0.x += a.x * rec.y;  ax0.y += a.y * rec.y;
                ax0.z += a.z * rec.y;  ax0.w += a.w * rec.y;
                ay0.x += a.x * rec.z;  ay0.y += a.y * rec.z;
                ay0.z += a.z * rec.z;  ay0.w += a.w * rec.z;
            }
        }
        // --- gather node 1 ---
        float4 ax1 = make_float4(0.f, 0.f, 0.f, 0.f);
        float4 ay1 = make_float4(0.f, 0.f, 0.f, 0.f);
        for (int c = 0; c < m1; c += 4) {
            #pragma unroll
            for (int u = 0; u < 4; u++) {
                int off = c + u;
                int idx = (off < len1) ? (beg1 + off) : E2;
                float4 rec = s_csr[idx];
                float4 a   = s_axial[__float_as_int(rec.x)];
                ax1.x += a.x * rec.y;  ax1.y += a.y * rec.y;
                ax1.z += a.z * rec.y;  ax1.w += a.w * rec.y;
                ay1.x += a.x * rec.z;  ay1.y += a.y * rec.z;
                ay1.z += a.z * rec.z;  ay1.w += a.w * rec.z;
            }
        }

        const float* ax0p = (const float*)&ax0;  const float* ay0p = (const float*)&ay0;
        const float* ax1p = (const float*)&ax1;  const float* ay1p = (const float*)&ay1;
        #pragma unroll
        for (int g = 0; g < G; g++) {
            float dx, dy;
            dx = ax0p[g] - qq0[g].x - rr0[g].x;  dy = ay0p[g] - qq0[g].y - rr0[g].y;
            acc += dx * dx + dy * dy;
            dx = ax1p[g] - qq1[g].x - rr1[g].x;  dy = ay1p[g] - qq1[g].y - rr1[g].y;
            acc += dx * dx + dy * dy;
        }
        __syncthreads();   // axial consumed before next build overwrites it
    }

    // --- block reduce ---
    #pragma unroll
    for (int o = 16; o > 0; o >>= 1)
        acc += __shfl_down_sync(0xffffffffu, acc, o);
    if ((tid & 31) == 0) s_warp[tid >> 5] = acc;
    __syncthreads();
    if (tid == 0) {
        float total = 0.f;
        #pragma unroll
        for (int w = 0; w < THREADS / 32; w++) total += s_warp[w];
        g_part[blockIdx.x] = total;
    }

    // --- last-block finalize (fixed-order double sum -> deterministic) ---
    __threadfence();
    if (tid == 0) {
        int old = atomicAdd(&g_ctr, 1);
        s_islast = (old == (int)gridDim.x - 1) ? 1 : 0;
    }
    __syncthreads();
    if (s_islast) {
        __threadfence();
        double* s_d = (double*)(dyn + OFF_CSR);   // overlay consumed CSR
        double d = 0.0;
        #pragma unroll
        for (int i = tid; i < NBLK; i += THREADS) d += (double)g_part[i];
        s_d[tid] = d;
        __syncthreads();
        #pragma unroll
        for (int s = THREADS / 2; s > 0; s >>= 1) {
            if (tid < s) s_d[tid] += s_d[tid + s];
            __syncthreads();
        }
        if (tid == 0) {
            out[0] = (float)(s_d[0] / ((double)B * (double)N_NODES * 2.0));
            g_ctr = 0;   // reset for next graph replay
        }
    }
}

extern "C" void kernel_launch(void* const* d_in, const int* in_sizes, int n_in,
                              void* d_out, int out_size) {
    const float* EA       = (const float*)d_in[0];
    const float* e        = (const float*)d_in[1];
    const float* q        = (const float*)d_in[2];
    const float* r        = (const float*)d_in[3];
    const float* vecs     = (const float*)d_in[4];
    const int*   node_ids = (const int*)d_in[5];
    const int*   elem_ids = (const int*)d_in[6];
    float* out = (float*)d_out;

    static int configured = 0;
    if (!configured) {
        cudaFuncSetAttribute(nel_main_kernel,
                             cudaFuncAttributeMaxDynamicSharedMemorySize,
                             SMEM_BYTES);
        configured = 1;
    }

    nel_setup_kernel<<<1, N_NODES>>>(node_ids, elem_ids, vecs);
    nel_main_kernel<<<NBLK, THREADS, SMEM_BYTES>>>(EA, e, q, r, out);
}